// round 14
// baseline (speedup 1.0000x reference)
#include <cuda_runtime.h>
#include <cuda_fp16.h>

#define NN 100000
#define EE 1200000
#define DD 64
#define DV (DD/4)        // 16 float4 per node row (f32)
#define HQ 8             // 8 uint4 per node row (fp16: 8 halves each)
#define SBS 1024
#define NBLK ((NN + SBS - 1) / SBS)   // 98
#define BINS 64

// ---- scratch (static device globals; no allocation at runtime) ----
__device__ int    g_is64;
__device__ int    g_total;
__device__ int    g_done;
__device__ int    g_cnt [NN];
__device__ int    g_off [NN];
__device__ int    g_cur [NN];
__device__ float  g_dinv[NN];
__device__ int    g_dbin[BINS];        // degree histogram
__device__ int    g_bincur[BINS];      // bin cursors (exclusive starts)
__device__ int    g_perm[NN];          // nodes grouped by degree bin
__device__ int2   g_csr [EE];          // CSR entry: {src, original edge id}
__device__ uint4  g_hW  [NN * HQ];     // fp16 prescaled dinv*w
__device__ uint4  g_hA  [NN * HQ];     // fp16 xs ping
__device__ uint4  g_hB  [NN * HQ];     // fp16 xs pong
__device__ uint4  g_hO  [NN * HQ];     // fp16 shadow of out (dot gathers)
__device__ float4 g_out [NN * DV];     // f32 out

// ---- helpers ----
__device__ __forceinline__ unsigned h2u(__half2 h) { return *(unsigned*)&h; }
__device__ __forceinline__ __half2 u2h(unsigned u) { return *(__half2*)&u; }

__device__ __forceinline__ uint4 pack_half8(float4 lo, float4 hi) {
    uint4 u;
    u.x = h2u(__floats2half2_rn(lo.x, lo.y));
    u.y = h2u(__floats2half2_rn(lo.z, lo.w));
    u.z = h2u(__floats2half2_rn(hi.x, hi.y));
    u.w = h2u(__floats2half2_rn(hi.z, hi.w));
    return u;
}
__device__ __forceinline__ void unpack_half8(uint4 u, float4& lo, float4& hi) {
    float2 a = __half22float2(u2h(u.x));
    float2 b = __half22float2(u2h(u.y));
    float2 c = __half22float2(u2h(u.z));
    float2 d = __half22float2(u2h(u.w));
    lo = make_float4(a.x, a.y, b.x, b.y);
    hi = make_float4(c.x, c.y, d.x, d.y);
}
#define ACC8(A, B, L, H) \
    A.x += L.x; A.y += L.y; A.z += L.z; A.w += L.w; \
    B.x += H.x; B.y += H.y; B.z += H.z; B.w += H.w;

__device__ __forceinline__ void decode_edge(const void* __restrict__ ei,
                                            int e, int& r, int& c) {
    if (g_is64) {
        const long long* p = (const long long*)ei;
        r = (int)p[e];
        c = (int)p[EE + e];
    } else {
        const int* p = (const int*)ei;
        r = p[e];
        c = p[EE + e];
    }
    if ((unsigned)r >= NN) r = 0;
    if ((unsigned)c >= NN) c = 0;
}

// ---- kernels ----

__global__ void prep0_kernel(const int* __restrict__ ei32) {
    int n = blockIdx.x * blockDim.x + threadIdx.x;
    if (n < NN) g_cnt[n] = 0;
    if (blockIdx.x == 0) {
        if (threadIdx.x == 0) { g_total = 0; g_done = 0; }
        if (threadIdx.x < BINS) g_dbin[threadIdx.x] = 0;
        int v = ei32[2 * threadIdx.x + 1];
        int any = __syncthreads_or(v != 0);
        if (threadIdx.x == 0) g_is64 = any ? 0 : 1;
    }
}

// histogram: reads ONLY the col half of edge_index
__global__ void prep_edges_kernel(const void* __restrict__ ei) {
    int e = blockIdx.x * blockDim.x + threadIdx.x;
    if (e < EE) {
        int c;
        if (g_is64) c = (int)((const long long*)ei)[EE + e];
        else        c = ((const int*)ei)[EE + e];
        if ((unsigned)c >= NN) c = 0;
        atomicAdd(&g_cnt[c], 1);
    }
}

// Segment allocation + dinv + degree histogram; last block scans the bins.
__global__ void scan_kernel() {
    __shared__ int wsum[32];
    __shared__ int base;
    __shared__ int sh_hist[BINS];
    __shared__ int s_last;
    int t    = threadIdx.x;
    int lane = t & 31;
    int warp = t >> 5;
    int i = blockIdx.x * SBS + t;
    if (t < BINS) sh_hist[t] = 0;
    int v = (i < NN) ? g_cnt[i] : 0;
    int x = v;
    #pragma unroll
    for (int d = 1; d < 32; d <<= 1) {
        int y = __shfl_up_sync(0xFFFFFFFFu, x, d);
        if (lane >= d) x += y;
    }
    if (lane == 31) wsum[warp] = x;
    __syncthreads();
    if (warp == 0) {
        int s = wsum[lane];
        #pragma unroll
        for (int d = 1; d < 32; d <<= 1) {
            int y = __shfl_up_sync(0xFFFFFFFFu, s, d);
            if (lane >= d) s += y;
        }
        wsum[lane] = s;
        if (lane == 31) base = atomicAdd(&g_total, s);
    }
    __syncthreads();
    int excl = x - v + ((warp > 0) ? wsum[warp - 1] : 0) + base;
    if (i < NN) {
        g_off[i] = excl;
        g_cur[i] = excl;
        g_dinv[i] = (v > 0) ? rsqrtf((float)v) : 0.0f;
        atomicAdd(&sh_hist[min(v, BINS - 1)], 1);
    }
    __syncthreads();
    if (t < BINS && sh_hist[t] > 0) atomicAdd(&g_dbin[t], sh_hist[t]);
    __threadfence();
    if (t == 0) {
        s_last = (atomicAdd(&g_done, 1) == NBLK - 1) ? 1 : 0;
        if (s_last) {
            int acc = 0;
            #pragma unroll
            for (int b = 0; b < BINS; ++b) {
                int d = g_dbin[b];
                g_bincur[b] = acc;
                acc += d;
            }
        }
    }
}

// Fused: CSR fill (edge-parallel) + convw + perm build (node ranges).
__global__ void fill_conv_kernel(const void* __restrict__ ei,
                                 const float4* __restrict__ w) {
    __shared__ int sh_cnt [BINS];
    __shared__ int sh_base[BINS];
    int tid = threadIdx.x;
    int e = blockIdx.x * blockDim.x + tid;

    // CSR fill
    if (e < EE) {
        int r, c;
        decode_edge(ei, e, r, c);
        int pos = atomicAdd(&g_cur[c], 1);
        g_csr[pos] = make_int2(r, e);
    }
    // convw ride-along
    if (e < NN * HQ) {
        int node = e >> 3;
        int c2   = e & 7;
        float di = g_dinv[node];
        float4 w0 = w[(node << 4) + (c2 << 1)];
        float4 w1 = w[(node << 4) + (c2 << 1) + 1];
        g_hW[e] = pack_half8(make_float4(di*w0.x, di*w0.y, di*w0.z, di*w0.w),
                             make_float4(di*w1.x, di*w1.y, di*w1.z, di*w1.w));
    }
    // perm build ride-along: blocks covering [0, NN) in node space
    int nfirst = blockIdx.x * blockDim.x;
    if (nfirst < NN) {
        if (tid < BINS) sh_cnt[tid] = 0;
        __syncthreads();
        int n = nfirst + tid;
        int bin = -1, local = 0;
        if (n < NN) {
            bin = min(g_cnt[n], BINS - 1);
            local = atomicAdd(&sh_cnt[bin], 1);
        }
        __syncthreads();
        if (tid < BINS && sh_cnt[tid] > 0)
            sh_base[tid] = atomicAdd(&g_bincur[tid], sh_cnt[tid]);
        __syncthreads();
        if (n < NN) g_perm[sh_base[bin] + local] = n;
    }
}

// Generic fp16 gather loop: unroll-4, two independent accumulator pairs.
__device__ __forceinline__ void gather_seg(const uint4* __restrict__ xs,
                                           int s, int e, int c,
                                           float4& alo, float4& ahi) {
    float4 blo = make_float4(0.f,0.f,0.f,0.f);
    float4 bhi = make_float4(0.f,0.f,0.f,0.f);
    for (; s + 3 < e; s += 4) {
        int r0 = g_csr[s].x,     r1 = g_csr[s + 1].x;
        int r2 = g_csr[s + 2].x, r3 = g_csr[s + 3].x;
        uint4 u0 = xs[(r0 << 3) + c];
        uint4 u1 = xs[(r1 << 3) + c];
        uint4 u2 = xs[(r2 << 3) + c];
        uint4 u3 = xs[(r3 << 3) + c];
        float4 l, h;
        unpack_half8(u0, l, h); ACC8(alo, ahi, l, h);
        unpack_half8(u1, l, h); ACC8(blo, bhi, l, h);
        unpack_half8(u2, l, h); ACC8(alo, ahi, l, h);
        unpack_half8(u3, l, h); ACC8(blo, bhi, l, h);
    }
    for (; s < e; ++s) {
        float4 l, h;
        unpack_half8(xs[(g_csr[s].x << 3) + c], l, h);
        ACC8(alo, ahi, l, h);
    }
    ACC8(alo, ahi, blo, bhi);
}

// Hop 1 fused with init (degree-balanced via perm)
__global__ void hop_first_kernel(const float4* __restrict__ w,
                                 const float* __restrict__ alpha) {
    int idx = blockIdx.x * blockDim.x + threadIdx.x;     // < NN*8
    if (idx >= NN * HQ) return;
    int node = g_perm[idx >> 3];
    int c    = idx & 7;

    float4 alo = make_float4(0.f,0.f,0.f,0.f);
    float4 ahi = make_float4(0.f,0.f,0.f,0.f);
    gather_seg(g_hW, g_off[node], g_cur[node], c, alo, ahi);

    float di = g_dinv[node];
    float a0 = alpha[0];
    float a1 = alpha[1];
    float4 xlo = make_float4(di*alo.x, di*alo.y, di*alo.z, di*alo.w);
    float4 xhi = make_float4(di*ahi.x, di*ahi.y, di*ahi.z, di*ahi.w);
    int ob = (node << 4) + (c << 1);
    float4 w0 = w[ob], w1 = w[ob + 1];
    g_out[ob]     = make_float4(a0*w0.x + a1*xlo.x, a0*w0.y + a1*xlo.y,
                                a0*w0.z + a1*xlo.z, a0*w0.w + a1*xlo.w);
    g_out[ob + 1] = make_float4(a0*w1.x + a1*xhi.x, a0*w1.y + a1*xhi.y,
                                a0*w1.z + a1*xhi.z, a0*w1.w + a1*xhi.w);
    g_hA[(node << 3) + c] =
        pack_half8(make_float4(di*xlo.x, di*xlo.y, di*xlo.z, di*xlo.w),
                   make_float4(di*xhi.x, di*xhi.y, di*xhi.z, di*xhi.w));
}

// Hops 2..K (degree-balanced)
__global__ void hop_kernel(const uint4* __restrict__ xs,
                           uint4* __restrict__ xs_dst,
                           const float* __restrict__ alpha, int k,
                           int write_next) {
    int idx = blockIdx.x * blockDim.x + threadIdx.x;     // < NN*8
    if (idx >= NN * HQ) return;
    int node = g_perm[idx >> 3];
    int c    = idx & 7;

    float4 alo = make_float4(0.f,0.f,0.f,0.f);
    float4 ahi = make_float4(0.f,0.f,0.f,0.f);
    gather_seg(xs, g_off[node], g_cur[node], c, alo, ahi);

    float di = g_dinv[node];
    float a  = alpha[k];
    float4 xlo = make_float4(di*alo.x, di*alo.y, di*alo.z, di*alo.w);
    float4 xhi = make_float4(di*ahi.x, di*ahi.y, di*ahi.z, di*ahi.w);
    int ob = (node << 4) + (c << 1);
    float4 o0 = g_out[ob], o1 = g_out[ob + 1];
    o0.x += a*xlo.x; o0.y += a*xlo.y; o0.z += a*xlo.z; o0.w += a*xlo.w;
    o1.x += a*xhi.x; o1.y += a*xhi.y; o1.z += a*xhi.z; o1.w += a*xhi.w;
    g_out[ob] = o0;
    g_out[ob + 1] = o1;
    if (write_next)
        xs_dst[(node << 3) + c] = pack_half8(
            make_float4(di*xlo.x, di*xlo.y, di*xlo.z, di*xlo.w),
            make_float4(di*xhi.x, di*xhi.y, di*xhi.z, di*xhi.w));
    else
        g_hO[(node << 3) + c] = pack_half8(o0, o1);
}

// CSR dot, 4-lane groups: each lane covers 32B of the row (2 uint4),
// reduction is 2 shfls. Degree bins make intra-warp trip counts uniform.
__global__ void dot_csr_kernel(float* __restrict__ res) {
    int idx = blockIdx.x * blockDim.x + threadIdx.x;     // < NN*4
    if (idx >= NN * 4) return;
    int node = g_perm[idx >> 2];
    int c    = idx & 3;                                  // 4 lanes per node
    int lane = threadIdx.x & 31;
    unsigned mask = 0xFu << (lane & 28);                 // this 4-lane group

    int ob = (node << 4) + (c << 2);                     // 4 float4 per lane
    float4 oi0 = g_out[ob];
    float4 oi1 = g_out[ob + 1];
    float4 oi2 = g_out[ob + 2];
    float4 oi3 = g_out[ob + 3];
    int s = g_off[node];
    int e = g_cur[node];
    if (s >= e) return;

    int hb = c << 1;                                     // 2 uint4 per lane
    int2  ce = g_csr[s];
    uint4 ua = g_hO[(ce.x << 3) + hb];
    uint4 ub = g_hO[(ce.x << 3) + hb + 1];
    for (++s; s < e; ++s) {
        int2  cen = g_csr[s];
        uint4 uan = g_hO[(cen.x << 3) + hb];             // prefetch next
        uint4 ubn = g_hO[(cen.x << 3) + hb + 1];
        float4 l0, h0, l1, h1;
        unpack_half8(ua, l0, h0);
        unpack_half8(ub, l1, h1);
        float p = oi0.x*l0.x + oi0.y*l0.y + oi0.z*l0.z + oi0.w*l0.w
                + oi1.x*h0.x + oi1.y*h0.y + oi1.z*h0.z + oi1.w*h0.w
                + oi2.x*l1.x + oi2.y*l1.y + oi2.z*l1.z + oi2.w*l1.w
                + oi3.x*h1.x + oi3.y*h1.y + oi3.z*h1.z + oi3.w*h1.w;
        p += __shfl_down_sync(mask, p, 2, 4);
        p += __shfl_down_sync(mask, p, 1, 4);
        if (c == 0) res[ce.y] = p;
        ce = cen; ua = uan; ub = ubn;
    }
    {
        float4 l0, h0, l1, h1;
        unpack_half8(ua, l0, h0);
        unpack_half8(ub, l1, h1);
        float p = oi0.x*l0.x + oi0.y*l0.y + oi0.z*l0.z + oi0.w*l0.w
                + oi1.x*h0.x + oi1.y*h0.y + oi1.z*h0.z + oi1.w*h0.w
                + oi2.x*l1.x + oi2.y*l1.y + oi2.z*l1.z + oi2.w*l1.w
                + oi3.x*h1.x + oi3.y*h1.y + oi3.z*h1.z + oi3.w*h1.w;
        p += __shfl_down_sync(mask, p, 2, 4);
        p += __shfl_down_sync(mask, p, 1, 4);
        if (c == 0) res[ce.y] = p;
    }
}

// ---- launch ----
extern "C" void kernel_launch(void* const* d_in, const int* in_sizes, int n_in,
                              void* d_out, int out_size) {
    const void*  ei    = nullptr;
    const float* w     = nullptr;
    const float* alpha = nullptr;
    for (int i = 0; i < n_in; ++i) {
        if (in_sizes[i] == 2 * EE)       ei    = d_in[i];
        else if (in_sizes[i] == NN * DD) w     = (const float*)d_in[i];
        else if (in_sizes[i] == 4)       alpha = (const float*)d_in[i];
    }
    float* res = (float*)d_out;

    void *p_hA, *p_hB;
    cudaGetSymbolAddress(&p_hA, g_hA);
    cudaGetSymbolAddress(&p_hB, g_hB);

    const int T = 256;
    const int gE  = (EE + T - 1) / T;
    const int gN  = (NN + T - 1) / T;
    const int gN8 = (NN * HQ + T - 1) / T;   // 3125
    const int gN4 = (NN * 4 + T - 1) / T;    // 1563

    prep0_kernel<<<gN, T>>>((const int*)ei);
    prep_edges_kernel<<<gE, T>>>(ei);
    scan_kernel<<<NBLK, SBS>>>();
    fill_conv_kernel<<<gE, T>>>(ei, (const float4*)w);

    uint4* hA = (uint4*)p_hA;
    uint4* hB = (uint4*)p_hB;

    hop_first_kernel<<<gN8, T>>>((const float4*)w, alpha);   // k=1 -> hA
    hop_kernel<<<gN8, T>>>(hA, hB, alpha, 2, 1);             // k=2 -> hB
    hop_kernel<<<gN8, T>>>(hB, hA, alpha, 3, 0);             // k=3 -> g_hO

    dot_csr_kernel<<<gN4, T>>>(res);
}

// round 15
// speedup vs baseline: 1.0474x; 1.0474x over previous
#include <cuda_runtime.h>
#include <cuda_fp16.h>

#define NN 100000
#define EE 1200000
#define DD 64
#define DV (DD/4)        // 16 float4 per node row (f32)
#define HQ 8             // 8 uint4 per node row (fp16: 8 halves each)
#define SBS 1024
#define NBLK ((NN + SBS - 1) / SBS)   // 98
#define BINS 64

// ---- scratch (static device globals; no allocation at runtime) ----
__device__ int    g_is64;
__device__ int    g_total;
__device__ int    g_done;
__device__ int    g_cnt [NN];
__device__ int    g_off [NN];
__device__ int    g_cur [NN];
__device__ float  g_dinv[NN];
__device__ int    g_dbin[BINS];        // degree histogram
__device__ int    g_bincur[BINS];      // bin cursors (exclusive starts)
__device__ int    g_perm[NN];          // nodes grouped by degree bin
__device__ int2   g_csr [EE];          // CSR entry: {src, original edge id}
__device__ uint4  g_hW  [NN * HQ];     // fp16 prescaled dinv*w
__device__ uint4  g_hA  [NN * HQ];     // fp16 dinv*x1
__device__ uint4  g_hB  [NN * HQ];     // fp16 dinv*x2
__device__ uint4  g_hO  [NN * HQ];     // fp16 shadow of out (dot gathers)
__device__ float4 g_out [NN * DV];     // f32 out

// ---- helpers ----
__device__ __forceinline__ unsigned h2u(__half2 h) { return *(unsigned*)&h; }
__device__ __forceinline__ __half2 u2h(unsigned u) { return *(__half2*)&u; }

__device__ __forceinline__ uint4 pack_half8(float4 lo, float4 hi) {
    uint4 u;
    u.x = h2u(__floats2half2_rn(lo.x, lo.y));
    u.y = h2u(__floats2half2_rn(lo.z, lo.w));
    u.z = h2u(__floats2half2_rn(hi.x, hi.y));
    u.w = h2u(__floats2half2_rn(hi.z, hi.w));
    return u;
}
__device__ __forceinline__ void unpack_half8(uint4 u, float4& lo, float4& hi) {
    float2 a = __half22float2(u2h(u.x));
    float2 b = __half22float2(u2h(u.y));
    float2 c = __half22float2(u2h(u.z));
    float2 d = __half22float2(u2h(u.w));
    lo = make_float4(a.x, a.y, b.x, b.y);
    hi = make_float4(c.x, c.y, d.x, d.y);
}
#define ACC8(A, B, L, H) \
    A.x += L.x; A.y += L.y; A.z += L.z; A.w += L.w; \
    B.x += H.x; B.y += H.y; B.z += H.z; B.w += H.w;

__device__ __forceinline__ void decode_edge(const void* __restrict__ ei,
                                            int e, int& r, int& c) {
    if (g_is64) {
        const long long* p = (const long long*)ei;
        r = (int)p[e];
        c = (int)p[EE + e];
    } else {
        const int* p = (const int*)ei;
        r = p[e];
        c = p[EE + e];
    }
    if ((unsigned)r >= NN) r = 0;
    if ((unsigned)c >= NN) c = 0;
}

// ---- kernels ----

__global__ void prep0_kernel(const int* __restrict__ ei32) {
    int n = blockIdx.x * blockDim.x + threadIdx.x;
    if (n < NN) g_cnt[n] = 0;
    if (blockIdx.x == 0) {
        if (threadIdx.x == 0) { g_total = 0; g_done = 0; }
        if (threadIdx.x < BINS) g_dbin[threadIdx.x] = 0;
        int v = ei32[2 * threadIdx.x + 1];
        int any = __syncthreads_or(v != 0);
        if (threadIdx.x == 0) g_is64 = any ? 0 : 1;
    }
}

// histogram: reads ONLY the col half of edge_index
__global__ void prep_edges_kernel(const void* __restrict__ ei) {
    int e = blockIdx.x * blockDim.x + threadIdx.x;
    if (e < EE) {
        int c;
        if (g_is64) c = (int)((const long long*)ei)[EE + e];
        else        c = ((const int*)ei)[EE + e];
        if ((unsigned)c >= NN) c = 0;
        atomicAdd(&g_cnt[c], 1);
    }
}

// Segment allocation + dinv + degree histogram; last block scans the bins.
__global__ void scan_kernel() {
    __shared__ int wsum[32];
    __shared__ int base;
    __shared__ int sh_hist[BINS];
    int t    = threadIdx.x;
    int lane = t & 31;
    int warp = t >> 5;
    int i = blockIdx.x * SBS + t;
    if (t < BINS) sh_hist[t] = 0;
    int v = (i < NN) ? g_cnt[i] : 0;
    int x = v;
    #pragma unroll
    for (int d = 1; d < 32; d <<= 1) {
        int y = __shfl_up_sync(0xFFFFFFFFu, x, d);
        if (lane >= d) x += y;
    }
    if (lane == 31) wsum[warp] = x;
    __syncthreads();
    if (warp == 0) {
        int s = wsum[lane];
        #pragma unroll
        for (int d = 1; d < 32; d <<= 1) {
            int y = __shfl_up_sync(0xFFFFFFFFu, s, d);
            if (lane >= d) s += y;
        }
        wsum[lane] = s;
        if (lane == 31) base = atomicAdd(&g_total, s);
    }
    __syncthreads();
    int excl = x - v + ((warp > 0) ? wsum[warp - 1] : 0) + base;
    if (i < NN) {
        g_off[i] = excl;
        g_cur[i] = excl;
        g_dinv[i] = (v > 0) ? rsqrtf((float)v) : 0.0f;
        atomicAdd(&sh_hist[min(v, BINS - 1)], 1);
    }
    __syncthreads();
    if (t < BINS && sh_hist[t] > 0) atomicAdd(&g_dbin[t], sh_hist[t]);
    __threadfence();
    if (t == 0) {
        if (atomicAdd(&g_done, 1) == NBLK - 1) {
            int acc = 0;
            #pragma unroll
            for (int b = 0; b < BINS; ++b) {
                int d = g_dbin[b];
                g_bincur[b] = acc;
                acc += d;
            }
        }
    }
}

// Fused: CSR fill (edge-parallel) + convw + perm build (node ranges).
__global__ void fill_conv_kernel(const void* __restrict__ ei,
                                 const float4* __restrict__ w) {
    __shared__ int sh_cnt [BINS];
    __shared__ int sh_base[BINS];
    int tid = threadIdx.x;
    int e = blockIdx.x * blockDim.x + tid;

    if (e < EE) {
        int r, c;
        decode_edge(ei, e, r, c);
        int pos = atomicAdd(&g_cur[c], 1);
        g_csr[pos] = make_int2(r, e);
    }
    if (e < NN * HQ) {
        int node = e >> 3;
        int c2   = e & 7;
        float di = g_dinv[node];
        float4 w0 = w[(node << 4) + (c2 << 1)];
        float4 w1 = w[(node << 4) + (c2 << 1) + 1];
        g_hW[e] = pack_half8(make_float4(di*w0.x, di*w0.y, di*w0.z, di*w0.w),
                             make_float4(di*w1.x, di*w1.y, di*w1.z, di*w1.w));
    }
    int nfirst = blockIdx.x * blockDim.x;
    if (nfirst < NN) {
        if (tid < BINS) sh_cnt[tid] = 0;
        __syncthreads();
        int n = nfirst + tid;
        int bin = -1, local = 0;
        if (n < NN) {
            bin = min(g_cnt[n], BINS - 1);
            local = atomicAdd(&sh_cnt[bin], 1);
        }
        __syncthreads();
        if (tid < BINS && sh_cnt[tid] > 0)
            sh_base[tid] = atomicAdd(&g_bincur[tid], sh_cnt[tid]);
        __syncthreads();
        if (n < NN) g_perm[sh_base[bin] + local] = n;
    }
}

// Generic fp16 gather loop: unroll-4, two independent accumulator pairs.
__device__ __forceinline__ void gather_seg(const uint4* __restrict__ xs,
                                           int s, int e, int c,
                                           float4& alo, float4& ahi) {
    float4 blo = make_float4(0.f,0.f,0.f,0.f);
    float4 bhi = make_float4(0.f,0.f,0.f,0.f);
    for (; s + 3 < e; s += 4) {
        int r0 = g_csr[s].x,     r1 = g_csr[s + 1].x;
        int r2 = g_csr[s + 2].x, r3 = g_csr[s + 3].x;
        uint4 u0 = xs[(r0 << 3) + c];
        uint4 u1 = xs[(r1 << 3) + c];
        uint4 u2 = xs[(r2 << 3) + c];
        uint4 u3 = xs[(r3 << 3) + c];
        float4 l, h;
        unpack_half8(u0, l, h); ACC8(alo, ahi, l, h);
        unpack_half8(u1, l, h); ACC8(blo, bhi, l, h);
        unpack_half8(u2, l, h); ACC8(alo, ahi, l, h);
        unpack_half8(u3, l, h); ACC8(blo, bhi, l, h);
    }
    for (; s < e; ++s) {
        float4 l, h;
        unpack_half8(xs[(g_csr[s].x << 3) + c], l, h);
        ACC8(alo, ahi, l, h);
    }
    ACC8(alo, ahi, blo, bhi);
}

// Hop 1 fused with init: out1 = a0*w + a1*x1; hA = fp16(dinv*x1)
__global__ void hop_first_kernel(const float4* __restrict__ w,
                                 const float* __restrict__ alpha) {
    int idx = blockIdx.x * blockDim.x + threadIdx.x;     // < NN*8
    if (idx >= NN * HQ) return;
    int node = g_perm[idx >> 3];
    int c    = idx & 7;

    float4 alo = make_float4(0.f,0.f,0.f,0.f);
    float4 ahi = make_float4(0.f,0.f,0.f,0.f);
    gather_seg(g_hW, g_off[node], g_cur[node], c, alo, ahi);

    float di = g_dinv[node];
    float a0 = alpha[0];
    float a1 = alpha[1];
    float4 xlo = make_float4(di*alo.x, di*alo.y, di*alo.z, di*alo.w);
    float4 xhi = make_float4(di*ahi.x, di*ahi.y, di*ahi.z, di*ahi.w);
    int ob = (node << 4) + (c << 1);
    float4 w0 = w[ob], w1 = w[ob + 1];
    g_out[ob]     = make_float4(a0*w0.x + a1*xlo.x, a0*w0.y + a1*xlo.y,
                                a0*w0.z + a1*xlo.z, a0*w0.w + a1*xlo.w);
    g_out[ob + 1] = make_float4(a0*w1.x + a1*xhi.x, a0*w1.y + a1*xhi.y,
                                a0*w1.z + a1*xhi.z, a0*w1.w + a1*xhi.w);
    g_hA[(node << 3) + c] =
        pack_half8(make_float4(di*xlo.x, di*xlo.y, di*xlo.z, di*xlo.w),
                   make_float4(di*xhi.x, di*xhi.y, di*xhi.z, di*xhi.w));
}

// Hop 2: NO g_out access. hB = fp16(dinv*x2) only.
__global__ void hop_mid_kernel() {
    int idx = blockIdx.x * blockDim.x + threadIdx.x;     // < NN*8
    if (idx >= NN * HQ) return;
    int node = g_perm[idx >> 3];
    int c    = idx & 7;

    float4 alo = make_float4(0.f,0.f,0.f,0.f);
    float4 ahi = make_float4(0.f,0.f,0.f,0.f);
    gather_seg(g_hA, g_off[node], g_cur[node], c, alo, ahi);

    float di = g_dinv[node];
    // x2 = di*acc ; store dinv*x2 = di*di*acc
    float d2 = di * di;
    g_hB[(node << 3) + c] =
        pack_half8(make_float4(d2*alo.x, d2*alo.y, d2*alo.z, d2*alo.w),
                   make_float4(d2*ahi.x, d2*ahi.y, d2*ahi.z, d2*ahi.w));
}

// Hop 3: out = out1 + a2*x2 + a3*x3, recovering x2 = hB[node]/dinv.
__global__ void hop_last_kernel(const float* __restrict__ alpha) {
    int idx = blockIdx.x * blockDim.x + threadIdx.x;     // < NN*8
    if (idx >= NN * HQ) return;
    int node = g_perm[idx >> 3];
    int c    = idx & 7;

    float4 alo = make_float4(0.f,0.f,0.f,0.f);
    float4 ahi = make_float4(0.f,0.f,0.f,0.f);
    gather_seg(g_hB, g_off[node], g_cur[node], c, alo, ahi);

    float di  = g_dinv[node];
    float rdi = (di > 0.0f) ? (1.0f / di) : 0.0f;
    float a2 = alpha[2];
    float a3 = alpha[3];
    // x3 = di * acc
    float4 x3lo = make_float4(di*alo.x, di*alo.y, di*alo.z, di*alo.w);
    float4 x3hi = make_float4(di*ahi.x, di*ahi.y, di*ahi.z, di*ahi.w);
    // x2 = hB[node] / di
    float4 blo, bhi;
    unpack_half8(g_hB[(node << 3) + c], blo, bhi);
    float4 x2lo = make_float4(rdi*blo.x, rdi*blo.y, rdi*blo.z, rdi*blo.w);
    float4 x2hi = make_float4(rdi*bhi.x, rdi*bhi.y, rdi*bhi.z, rdi*bhi.w);

    int ob = (node << 4) + (c << 1);
    float4 o0 = g_out[ob], o1 = g_out[ob + 1];
    o0.x += a2*x2lo.x + a3*x3lo.x; o0.y += a2*x2lo.y + a3*x3lo.y;
    o0.z += a2*x2lo.z + a3*x3lo.z; o0.w += a2*x2lo.w + a3*x3lo.w;
    o1.x += a2*x2hi.x + a3*x3hi.x; o1.y += a2*x2hi.y + a3*x3hi.y;
    o1.z += a2*x2hi.z + a3*x3hi.z; o1.w += a2*x2hi.w + a3*x3hi.w;
    g_out[ob] = o0;
    g_out[ob + 1] = o1;
    g_hO[(node << 3) + c] = pack_half8(o0, o1);
}

// CSR dot, 8-lane groups (R13 form) with software pipelining.
__global__ void dot_csr_kernel(float* __restrict__ res) {
    int idx = blockIdx.x * blockDim.x + threadIdx.x;     // < NN*8
    if (idx >= NN * HQ) return;
    int node = g_perm[idx >> 3];
    int c    = idx & 7;
    int lane = threadIdx.x & 31;
    unsigned mask = 0xFFu << (lane & 24);                // this 8-lane group

    int ob = (node << 4) + (c << 1);
    float4 oi0 = g_out[ob];
    float4 oi1 = g_out[ob + 1];
    int s = g_off[node];
    int e = g_cur[node];
    if (s >= e) return;

    int2  ce = g_csr[s];
    uint4 u  = g_hO[(ce.x << 3) + c];
    for (++s; s < e; ++s) {
        int2  cen = g_csr[s];
        uint4 un  = g_hO[(cen.x << 3) + c];   // prefetch next
        float4 lo, hi;
        unpack_half8(u, lo, hi);
        float p = oi0.x*lo.x + oi0.y*lo.y + oi0.z*lo.z + oi0.w*lo.w
                + oi1.x*hi.x + oi1.y*hi.y + oi1.z*hi.z + oi1.w*hi.w;
        p += __shfl_down_sync(mask, p, 4, 8);
        p += __shfl_down_sync(mask, p, 2, 8);
        p += __shfl_down_sync(mask, p, 1, 8);
        if (c == 0) res[ce.y] = p;
        ce = cen; u = un;
    }
    {
        float4 lo, hi;
        unpack_half8(u, lo, hi);
        float p = oi0.x*lo.x + oi0.y*lo.y + oi0.z*lo.z + oi0.w*lo.w
                + oi1.x*hi.x + oi1.y*hi.y + oi1.z*hi.z + oi1.w*hi.w;
        p += __shfl_down_sync(mask, p, 4, 8);
        p += __shfl_down_sync(mask, p, 2, 8);
        p += __shfl_down_sync(mask, p, 1, 8);
        if (c == 0) res[ce.y] = p;
    }
}

// ---- launch ----
extern "C" void kernel_launch(void* const* d_in, const int* in_sizes, int n_in,
                              void* d_out, int out_size) {
    const void*  ei    = nullptr;
    const float* w     = nullptr;
    const float* alpha = nullptr;
    for (int i = 0; i < n_in; ++i) {
        if (in_sizes[i] == 2 * EE)       ei    = d_in[i];
        else if (in_sizes[i] == NN * DD) w     = (const float*)d_in[i];
        else if (in_sizes[i] == 4)       alpha = (const float*)d_in[i];
    }
    float* res = (float*)d_out;

    const int T = 256;
    const int gE  = (EE + T - 1) / T;
    const int gN  = (NN + T - 1) / T;
    const int gN8 = (NN * HQ + T - 1) / T;   // 3125

    prep0_kernel<<<gN, T>>>((const int*)ei);
    prep_edges_kernel<<<gE, T>>>(ei);
    scan_kernel<<<NBLK, SBS>>>();
    fill_conv_kernel<<<gE, T>>>(ei, (const float4*)w);

    hop_first_kernel<<<gN8, T>>>((const float4*)w, alpha);   // k=1 -> out1, hA
    hop_mid_kernel<<<gN8, T>>>();                            // k=2 -> hB only
    hop_last_kernel<<<gN8, T>>>(alpha);                      // k=3 -> out, hO

    dot_csr_kernel<<<gN8, T>>>(res);
}